// round 2
// baseline (speedup 1.0000x reference)
#include <cuda_runtime.h>

// Problem constants (fixed by the reference)
#define BSZ   2
#define LEN   2048
#define DQ    512
#define SQ    4
#define SH    2                  // s-lanes per thread (SQ/2)
#define NC    128                // number of chunks along L
#define CHUNK (LEN / NC)         // 16 steps per chunk
#define EPSQ  1e-6f

// Scratch: chunk summaries and carries, laid out [b][chunk][s][d].
__device__ float4 g_Q  [BSZ * NC * SQ * DQ];
__device__ float4 g_H  [BSZ * NC * SQ * DQ];
__device__ float4 g_Hin[BSZ * NC * SQ * DQ];

// ---------------------------------------------------------------------------
// Quaternion helpers
// ---------------------------------------------------------------------------
__device__ __forceinline__ float4 qmuladd(const float4 a, const float4 b, const float4 c) {
    float4 r;
    r.x = fmaf(a.x, b.x, fmaf(-a.y, b.y, fmaf(-a.z, b.z, fmaf(-a.w, b.w, c.x))));
    r.y = fmaf(a.x, b.y, fmaf( a.y, b.x, fmaf( a.z, b.w, fmaf(-a.w, b.z, c.y))));
    r.z = fmaf(a.x, b.z, fmaf(-a.y, b.w, fmaf( a.z, b.x, fmaf( a.w, b.y, c.z))));
    r.w = fmaf(a.x, b.w, fmaf( a.y, b.z, fmaf(-a.z, b.y, fmaf( a.w, b.x, c.w))));
    return r;
}
__device__ __forceinline__ float4 qmul(const float4 a, const float4 b) {
    return qmuladd(a, b, make_float4(0.f, 0.f, 0.f, 0.f));
}

__device__ __forceinline__ float frcp_fast(float x) {
    float r;
    asm("rcp.approx.f32 %0, %1;" : "=f"(r) : "f"(x));
    return r * (2.0f - x * r);
}

// Per-step transition/injection math (optimized):
//   w    = dtv * ah                 (ah = 0.5*A)
//   n2   = (1-w_r)^2 + |w_v|^2 + eps ; rinv = 1/n2 ; r2 = 2*rinv
//   q    = (omr*r2 - 1, w_i*r2, w_j*r2, w_k*r2)
//   g    = (omr, w_v) * (dt*rinv)
//   Bu   = (g (x) B) (x) u
__device__ __forceinline__ void step_qbu(const float dtv, const float4 ah,
                                         const float4 Bq, const float4 uu,
                                         float4& q, float4& Bu) {
    const float wr = dtv * ah.x, wi = dtv * ah.y, wj = dtv * ah.z, wk = dtv * ah.w;
    const float omr = 1.0f - wr;
    const float vve = fmaf(wi, wi, fmaf(wj, wj, fmaf(wk, wk, EPSQ)));
    const float n2  = fmaf(omr, omr, vve);
    const float rinv = frcp_fast(n2);
    const float r2 = rinv + rinv;
    q = make_float4(fmaf(omr, r2, -1.0f), wi * r2, wj * r2, wk * r2);
    const float e = dtv * rinv;
    const float4 g = make_float4(omr * e, wi * e, wj * e, wk * e);
    Bu = qmul(qmul(g, Bq), uu);
}

__device__ __forceinline__ void load_ah2(const float* __restrict__ A_log,
                                         const float* __restrict__ A_i,
                                         const float* __restrict__ A_j,
                                         const float* __restrict__ A_k,
                                         int d, int s0, float4 ah[SH]) {
#pragma unroll
    for (int s = 0; s < SH; s++) {
        const int ai = d * SQ + s0 + s;
        ah[s] = make_float4(-0.5f * expf(A_log[ai]), 0.5f * A_i[ai],
                             0.5f * A_j[ai],          0.5f * A_k[ai]);
    }
}

// Thread decomposition for the heavy kernels:
//   lane bits [0:4) = d low 4 bits, lane bit 4 = s-half, upper = d-high, c, b.
struct Decomp { int b, c, d, s0, hbit; };
__device__ __forceinline__ Decomp decomp(int gt) {
    Decomp r;
    const int lane16 = gt & 15;
    r.hbit = (gt >> 4) & 1;
    const int rest = gt >> 5;              // [0, BSZ*NC*(DQ/16))
    const int dhi = rest & 31;             // DQ/16 = 32
    r.c = (rest >> 5) & (NC - 1);
    r.b = rest >> 12;                      // 5 + 7 bits
    r.d = dhi * 16 + lane16;
    r.s0 = r.hbit * SH;
    return r;
}

// ---------------------------------------------------------------------------
// K1: per-(b, chunk, d, s-half) thread — chunk transforms (Q_total, H_total)
// ---------------------------------------------------------------------------
__global__ void __launch_bounds__(256)
k_summary(const float* __restrict__ u, const float* __restrict__ dt,
          const float* __restrict__ Bin,
          const float* __restrict__ A_log, const float* __restrict__ A_i,
          const float* __restrict__ A_j,  const float* __restrict__ A_k)
{
    const Decomp de = decomp(blockIdx.x * blockDim.x + threadIdx.x);

    float4 ah[SH];
    load_ah2(A_log, A_i, A_j, A_k, de.d, de.s0, ah);

    const float4* __restrict__ u4 = (const float4*)u;
    const float4* __restrict__ B4 = (const float4*)Bin;

    const int t0 = de.c * CHUNK;
    float4 Q[SH], H[SH];

    // Peel first iteration: Q = q, H = Bu.
    {
        const int td = de.b * LEN + t0;
        const float  dtv = dt[td * DQ + de.d];
        const float4 uu  = u4[td * DQ + de.d];
#pragma unroll
        for (int s = 0; s < SH; s++) {
            const float4 Bq = B4[td * SQ + de.s0 + s];
            step_qbu(dtv, ah[s], Bq, uu, Q[s], H[s]);
        }
    }

#pragma unroll 3
    for (int i = 1; i < CHUNK; i++) {
        const int td = de.b * LEN + t0 + i;
        const float  dtv = dt[td * DQ + de.d];
        const float4 uu  = u4[td * DQ + de.d];
#pragma unroll
        for (int s = 0; s < SH; s++) {
            const float4 Bq = B4[td * SQ + de.s0 + s];
            float4 q, Bu;
            step_qbu(dtv, ah[s], Bq, uu, q, Bu);
            H[s] = qmuladd(q, H[s], Bu);
            Q[s] = qmul(q, Q[s]);
        }
    }

#pragma unroll
    for (int s = 0; s < SH; s++) {
        const int idx = ((de.b * NC + de.c) * SQ + de.s0 + s) * DQ + de.d;
        g_Q[idx] = Q[s];
        g_H[idx] = H[s];
    }
}

// ---------------------------------------------------------------------------
// K2: per-(b, s, d) thread — sequential scan over NC chunk transforms.
// ---------------------------------------------------------------------------
__global__ void __launch_bounds__(256)
k_carry()
{
    const int tid = blockIdx.x * blockDim.x + threadIdx.x;
    const int d = tid % DQ;
    const int s = (tid / DQ) % SQ;
    const int b = tid / (DQ * SQ);
    if (b >= BSZ) return;

    float4 carry = make_float4(0.f, 0.f, 0.f, 0.f);
#pragma unroll 4
    for (int c = 0; c < NC; c++) {
        const int idx = ((b * NC + c) * SQ + s) * DQ + d;
        g_Hin[idx] = carry;
        carry = qmuladd(g_Q[idx], carry, g_H[idx]);
    }
}

// ---------------------------------------------------------------------------
// K3: per-(b, chunk, d, s-half) thread — recompute with carry, emit y.
//     Pair-sum over s-halves via shfl_xor(16); h==0 lanes store float4.
// ---------------------------------------------------------------------------
__global__ void __launch_bounds__(256)
k_final(const float* __restrict__ u, const float* __restrict__ dt,
        const float* __restrict__ Bin, const float* __restrict__ Cin,
        const float* __restrict__ A_log, const float* __restrict__ A_i,
        const float* __restrict__ A_j,  const float* __restrict__ A_k,
        float* __restrict__ out)
{
    const Decomp de = decomp(blockIdx.x * blockDim.x + threadIdx.x);

    float4 ah[SH];
    load_ah2(A_log, A_i, A_j, A_k, de.d, de.s0, ah);

    float4 h[SH];
#pragma unroll
    for (int s = 0; s < SH; s++)
        h[s] = g_Hin[((de.b * NC + de.c) * SQ + de.s0 + s) * DQ + de.d];

    const float4* __restrict__ u4 = (const float4*)u;
    const float4* __restrict__ B4 = (const float4*)Bin;
    const float4* __restrict__ C4 = (const float4*)Cin;
    float4* __restrict__ o4 = (float4*)out;

    const int t0 = de.c * CHUNK;
#pragma unroll 4
    for (int i = 0; i < CHUNK; i++) {
        const int td = de.b * LEN + t0 + i;
        const float  dtv = dt[td * DQ + de.d];
        const float4 uu  = u4[td * DQ + de.d];
        float4 y = make_float4(0.f, 0.f, 0.f, 0.f);
#pragma unroll
        for (int s = 0; s < SH; s++) {
            const float4 Bq = B4[td * SQ + de.s0 + s];
            const float4 Cq = C4[td * SQ + de.s0 + s];
            float4 q, Bu;
            step_qbu(dtv, ah[s], Bq, uu, q, Bu);
            h[s] = qmuladd(q, h[s], Bu);
            y = qmuladd(Cq, h[s], y);
        }
        // Pair-reduce across s-halves (lane bit 4).
        y.x += __shfl_xor_sync(0xffffffffu, y.x, 16);
        y.y += __shfl_xor_sync(0xffffffffu, y.y, 16);
        y.z += __shfl_xor_sync(0xffffffffu, y.z, 16);
        y.w += __shfl_xor_sync(0xffffffffu, y.w, 16);
        if (de.hbit == 0)
            o4[td * DQ + de.d] = y;
    }
}

// ---------------------------------------------------------------------------
// Launch
// ---------------------------------------------------------------------------
extern "C" void kernel_launch(void* const* d_in, const int* in_sizes, int n_in,
                              void* d_out, int out_size)
{
    const float* u     = (const float*)d_in[0];
    const float* dt    = (const float*)d_in[1];
    const float* Bin   = (const float*)d_in[2];
    const float* Cin   = (const float*)d_in[3];
    const float* A_log = (const float*)d_in[4];
    const float* A_i   = (const float*)d_in[5];
    const float* A_j   = (const float*)d_in[6];
    const float* A_k   = (const float*)d_in[7];
    float* out = (float*)d_out;

    const int heavy_threads = BSZ * NC * DQ * 2;   // 262144
    const int carry_threads = BSZ * SQ * DQ;       // 4096

    k_summary<<<heavy_threads / 256, 256>>>(u, dt, Bin, A_log, A_i, A_j, A_k);
    k_carry<<<(carry_threads + 255) / 256, 256>>>();
    k_final<<<heavy_threads / 256, 256>>>(u, dt, Bin, Cin, A_log, A_i, A_j, A_k, out);
}

// round 3
// speedup vs baseline: 1.0623x; 1.0623x over previous
#include <cuda_runtime.h>

// Problem constants (fixed by the reference)
#define BSZ   2
#define LEN   2048
#define DQ    512
#define SQ    4
#define SH    2                  // s-lanes per thread (SQ/2)
#define NC    64                 // number of chunks along L
#define CHUNK (LEN / NC)         // 32 steps per chunk
#define EPSQ  1e-6f

// Scratch: chunk summaries and carries, laid out [b][chunk][s][d].
__device__ float4 g_Q  [BSZ * NC * SQ * DQ];
__device__ float4 g_H  [BSZ * NC * SQ * DQ];
__device__ float4 g_Hin[BSZ * NC * SQ * DQ];

// ---------------------------------------------------------------------------
// Quaternion helpers
// ---------------------------------------------------------------------------
__device__ __forceinline__ float4 qmuladd(const float4 a, const float4 b, const float4 c) {
    float4 r;
    r.x = fmaf(a.x, b.x, fmaf(-a.y, b.y, fmaf(-a.z, b.z, fmaf(-a.w, b.w, c.x))));
    r.y = fmaf(a.x, b.y, fmaf( a.y, b.x, fmaf( a.z, b.w, fmaf(-a.w, b.z, c.y))));
    r.z = fmaf(a.x, b.z, fmaf(-a.y, b.w, fmaf( a.z, b.x, fmaf( a.w, b.y, c.z))));
    r.w = fmaf(a.x, b.w, fmaf( a.y, b.z, fmaf(-a.z, b.y, fmaf( a.w, b.x, c.w))));
    return r;
}
__device__ __forceinline__ float4 qmul(const float4 a, const float4 b) {
    return qmuladd(a, b, make_float4(0.f, 0.f, 0.f, 0.f));
}

__device__ __forceinline__ float frcp_fast(float x) {
    float r;
    asm("rcp.approx.f32 %0, %1;" : "=f"(r) : "f"(x));
    return r * (2.0f - x * r);
}

// Per-step transition quaternion:
//   w  = dtv * ah                (ah = 0.5*A)
//   n2 = (1-w_r)^2 + |w_v|^2 + eps ; r2 = 2/n2
//   q  = (omr*r2 - 1, w_i*r2, w_j*r2, w_k*r2)
// Injection (algebraic identity, g = den_inv*dt = (dt/2)(q + ident)):
//   u_s = u*(dt/2)  [shared across s]
//   Bu0 = B (x) u_s
//   Bu  = q (x) Bu0 + Bu0
__device__ __forceinline__ float4 step_q(const float dtv, const float4 ah) {
    const float wr = dtv * ah.x, wi = dtv * ah.y, wj = dtv * ah.z, wk = dtv * ah.w;
    const float omr = 1.0f - wr;
    const float vve = fmaf(wi, wi, fmaf(wj, wj, fmaf(wk, wk, EPSQ)));
    const float n2  = fmaf(omr, omr, vve);
    const float rinv = frcp_fast(n2);
    const float r2 = rinv + rinv;
    return make_float4(fmaf(omr, r2, -1.0f), wi * r2, wj * r2, wk * r2);
}

__device__ __forceinline__ void load_ah2(const float* __restrict__ A_log,
                                         const float* __restrict__ A_i,
                                         const float* __restrict__ A_j,
                                         const float* __restrict__ A_k,
                                         int d, int s0, float4 ah[SH]) {
#pragma unroll
    for (int s = 0; s < SH; s++) {
        const int ai = d * SQ + s0 + s;
        ah[s] = make_float4(-0.5f * expf(A_log[ai]), 0.5f * A_i[ai],
                             0.5f * A_j[ai],          0.5f * A_k[ai]);
    }
}

// Thread decomposition for the heavy kernels:
//   lane bits [0:4) = d low 4 bits, lane bit 4 = s-half, upper = d-high, c, b.
struct Decomp { int b, c, d, s0, hbit; };
__device__ __forceinline__ Decomp decomp(int gt) {
    Decomp r;
    const int lane16 = gt & 15;
    r.hbit = (gt >> 4) & 1;
    const int rest = gt >> 5;
    const int dhi = rest & 31;             // DQ/16 = 32
    r.c = (rest >> 5) & (NC - 1);          // NC = 64
    r.b = rest >> 11;
    r.d = dhi * 16 + lane16;
    r.s0 = r.hbit * SH;
    return r;
}

// ---------------------------------------------------------------------------
// K1: per-(b, chunk, d, s-half) thread — chunk transforms (Q_total, H_total)
// ---------------------------------------------------------------------------
__global__ void __launch_bounds__(256)
k_summary(const float* __restrict__ u, const float* __restrict__ dt,
          const float* __restrict__ Bin,
          const float* __restrict__ A_log, const float* __restrict__ A_i,
          const float* __restrict__ A_j,  const float* __restrict__ A_k)
{
    const Decomp de = decomp(blockIdx.x * blockDim.x + threadIdx.x);

    float4 ah[SH];
    load_ah2(A_log, A_i, A_j, A_k, de.d, de.s0, ah);

    const float4* __restrict__ u4 = (const float4*)u;
    const float4* __restrict__ B4 = (const float4*)Bin;

    const int t0 = de.c * CHUNK;
    float4 Q[SH], H[SH];

    // Peel first iteration: Q = q, H = Bu.
    {
        const int td = de.b * LEN + t0;
        const float  dtv = dt[td * DQ + de.d];
        const float4 uu  = u4[td * DQ + de.d];
        const float  hdt = 0.5f * dtv;
        const float4 us  = make_float4(uu.x * hdt, uu.y * hdt, uu.z * hdt, uu.w * hdt);
#pragma unroll
        for (int s = 0; s < SH; s++) {
            const float4 Bq = B4[td * SQ + de.s0 + s];
            const float4 q  = step_q(dtv, ah[s]);
            const float4 Bu0 = qmul(Bq, us);
            Q[s] = q;
            H[s] = qmuladd(q, Bu0, Bu0);
        }
    }

#pragma unroll 2
    for (int i = 1; i < CHUNK; i++) {
        const int td = de.b * LEN + t0 + i;
        const float  dtv = dt[td * DQ + de.d];
        const float4 uu  = u4[td * DQ + de.d];
        const float  hdt = 0.5f * dtv;
        const float4 us  = make_float4(uu.x * hdt, uu.y * hdt, uu.z * hdt, uu.w * hdt);
#pragma unroll
        for (int s = 0; s < SH; s++) {
            const float4 Bq = B4[td * SQ + de.s0 + s];
            const float4 q  = step_q(dtv, ah[s]);
            const float4 Bu0 = qmul(Bq, us);
            const float4 Bu  = qmuladd(q, Bu0, Bu0);
            H[s] = qmuladd(q, H[s], Bu);
            Q[s] = qmul(q, Q[s]);
        }
    }

#pragma unroll
    for (int s = 0; s < SH; s++) {
        const int idx = ((de.b * NC + de.c) * SQ + de.s0 + s) * DQ + de.d;
        g_Q[idx] = Q[s];
        g_H[idx] = H[s];
    }
}

// ---------------------------------------------------------------------------
// K2: per-(b, s, d) thread — sequential scan over NC chunk transforms.
// ---------------------------------------------------------------------------
__global__ void __launch_bounds__(256)
k_carry()
{
    const int tid = blockIdx.x * blockDim.x + threadIdx.x;
    const int d = tid % DQ;
    const int s = (tid / DQ) % SQ;
    const int b = tid / (DQ * SQ);
    if (b >= BSZ) return;

    float4 carry = make_float4(0.f, 0.f, 0.f, 0.f);
#pragma unroll 4
    for (int c = 0; c < NC; c++) {
        const int idx = ((b * NC + c) * SQ + s) * DQ + d;
        g_Hin[idx] = carry;
        carry = qmuladd(g_Q[idx], carry, g_H[idx]);
    }
}

// ---------------------------------------------------------------------------
// K3: per-(b, chunk, d, s-half) thread — recompute with carry, emit y.
//     Pair-sum over s-halves via shfl_xor(16); hbit==0 lanes store float4.
// ---------------------------------------------------------------------------
__global__ void __launch_bounds__(256)
k_final(const float* __restrict__ u, const float* __restrict__ dt,
        const float* __restrict__ Bin, const float* __restrict__ Cin,
        const float* __restrict__ A_log, const float* __restrict__ A_i,
        const float* __restrict__ A_j,  const float* __restrict__ A_k,
        float* __restrict__ out)
{
    const Decomp de = decomp(blockIdx.x * blockDim.x + threadIdx.x);

    float4 ah[SH];
    load_ah2(A_log, A_i, A_j, A_k, de.d, de.s0, ah);

    float4 h[SH];
#pragma unroll
    for (int s = 0; s < SH; s++)
        h[s] = g_Hin[((de.b * NC + de.c) * SQ + de.s0 + s) * DQ + de.d];

    const float4* __restrict__ u4 = (const float4*)u;
    const float4* __restrict__ B4 = (const float4*)Bin;
    const float4* __restrict__ C4 = (const float4*)Cin;
    float4* __restrict__ o4 = (float4*)out;

    const int t0 = de.c * CHUNK;
#pragma unroll 2
    for (int i = 0; i < CHUNK; i++) {
        const int td = de.b * LEN + t0 + i;
        const float  dtv = dt[td * DQ + de.d];
        const float4 uu  = u4[td * DQ + de.d];
        const float  hdt = 0.5f * dtv;
        const float4 us  = make_float4(uu.x * hdt, uu.y * hdt, uu.z * hdt, uu.w * hdt);
        float4 y = make_float4(0.f, 0.f, 0.f, 0.f);
#pragma unroll
        for (int s = 0; s < SH; s++) {
            const float4 Bq = B4[td * SQ + de.s0 + s];
            const float4 Cq = C4[td * SQ + de.s0 + s];
            const float4 q  = step_q(dtv, ah[s]);
            const float4 Bu0 = qmul(Bq, us);
            const float4 Bu  = qmuladd(q, Bu0, Bu0);
            h[s] = qmuladd(q, h[s], Bu);
            y = qmuladd(Cq, h[s], y);
        }
        // Pair-reduce across s-halves (lane bit 4).
        y.x += __shfl_xor_sync(0xffffffffu, y.x, 16);
        y.y += __shfl_xor_sync(0xffffffffu, y.y, 16);
        y.z += __shfl_xor_sync(0xffffffffu, y.z, 16);
        y.w += __shfl_xor_sync(0xffffffffu, y.w, 16);
        if (de.hbit == 0)
            o4[td * DQ + de.d] = y;
    }
}

// ---------------------------------------------------------------------------
// Launch
// ---------------------------------------------------------------------------
extern "C" void kernel_launch(void* const* d_in, const int* in_sizes, int n_in,
                              void* d_out, int out_size)
{
    const float* u     = (const float*)d_in[0];
    const float* dt    = (const float*)d_in[1];
    const float* Bin   = (const float*)d_in[2];
    const float* Cin   = (const float*)d_in[3];
    const float* A_log = (const float*)d_in[4];
    const float* A_i   = (const float*)d_in[5];
    const float* A_j   = (const float*)d_in[6];
    const float* A_k   = (const float*)d_in[7];
    float* out = (float*)d_out;

    const int heavy_threads = BSZ * NC * DQ * 2;   // 131072
    const int carry_threads = BSZ * SQ * DQ;       // 4096

    k_summary<<<heavy_threads / 256, 256>>>(u, dt, Bin, A_log, A_i, A_j, A_k);
    k_carry<<<(carry_threads + 255) / 256, 256>>>();
    k_final<<<heavy_threads / 256, 256>>>(u, dt, Bin, Cin, A_log, A_i, A_j, A_k, out);
}